// round 3
// baseline (speedup 1.0000x reference)
#include <cuda_runtime.h>

// HartleySpectralConv2d: B=16, CI=CO=64, H=W=256, modes 64x64.
// Partial DHT as dense GEMMs; inner loops use packed fp32 FFMA2 (fma.rn.f32x2).

using u64 = unsigned long long;

__device__ __forceinline__ u64 pack2(float lo, float hi) {
    u64 r; asm("mov.b64 %0, {%1, %2};" : "=l"(r) : "f"(lo), "f"(hi)); return r;
}
__device__ __forceinline__ float2 u2f(u64 v) {
    float2 f; asm("mov.b64 {%0, %1}, %2;" : "=f"(f.x), "=f"(f.y) : "l"(v)); return f;
}
__device__ __forceinline__ void fma2(u64& d, u64 a, u64 b) {
    asm("fma.rn.f32x2 %0, %1, %2, %0;" : "+l"(d) : "l"(a), "l"(b));
}

__device__ float g_T1[256 * 128];        // [n][j]   j<64: cos(2pi(j-32)n/256), j>=64: sin
__device__ float g_T2[128 * 256];        // [j][m]
__device__ float g_T4[64 * 512];         // [s2][comp*256+n]
__device__ float g_A5[256 * 128];        // [m][2*s1+comp]
__device__ float g_Wt[4096 * 4096];      // [s1*64+s2][i*64+o]
__device__ float g_U[1024 * 256 * 128];  // [img][m][j]
__device__ float g_CS[2 * 4096 * 1024];  // [comp][mode][ci*16 + b]
__device__ float g_Tt[1024 * 4096];      // [b*64+o][mode]
__device__ float g_V[1024 * 128 * 256];  // [img][s1*2+comp][n]

// ---------------- K0: trig tables ----------------
__global__ void k_tables() {
    int a = blockIdx.x;      // 0..255
    int b = threadIdx.x;     // 0..127
    int s = b & 63;
    int k = s - 32;
    int q = ((k * a) % 256 + 256) % 256;
    float sv, cv;
    sincospif((float)q * (1.0f / 128.0f), &sv, &cv);
    float v = (b < 64) ? cv : sv;
    g_T1[a * 128 + b] = v;
    g_T2[b * 256 + a] = v;
    g_T4[s * 512 + (b >> 6) * 256 + a] = v;
    g_A5[a * 128 + 2 * s + (b >> 6)] = (b < 64) ? (cv + sv) : (cv - sv);
}

// ---------------- Kw: weight transpose ----------------
__global__ void k_wt(const float* __restrict__ w) {
    __shared__ float tile[32][33];
    int x0 = blockIdx.x * 32;
    int y0 = blockIdx.y * 32;
    int tx = threadIdx.x, ty = threadIdx.y;
#pragma unroll
    for (int r = 0; r < 32; r += 8)
        tile[ty + r][tx] = w[(y0 + ty + r) * 4096 + x0 + tx];
    __syncthreads();
#pragma unroll
    for (int r = 0; r < 32; r += 8)
        g_Wt[(x0 + ty + r) * 4096 + y0 + tx] = tile[tx][ty + r];
}

// ---------------- K1: forward stage 1 ----------------
__global__ __launch_bounds__(256) void k_fwd1(const float* __restrict__ x) {
    __shared__ float As[128 * 32];
    __shared__ float Bs[32 * 128];
    const int row0 = blockIdx.x * 128;
    const int tid = threadIdx.x;
    const int ty = tid >> 4, tx = tid & 15;

    float4 pa[4], pb[4];
#pragma unroll
    for (int t = 0; t < 4; t++) {
        int f = tid + t * 256;
        int r = f >> 3, c = (f & 7) << 2;
        pa[t] = *(const float4*)&x[(row0 + r) * 256 + c];
        int kk = f >> 5, c2 = (f & 31) << 2;
        pb[t] = *(const float4*)&g_T1[kk * 128 + c2];
    }
    u64 acc[8][4];
#pragma unroll
    for (int i = 0; i < 8; i++)
#pragma unroll
        for (int j = 0; j < 4; j++) acc[i][j] = 0ull;

    for (int k0 = 0; k0 < 256; k0 += 32) {
        __syncthreads();
#pragma unroll
        for (int t = 0; t < 4; t++) {
            int f = tid + t * 256;
            int r = f >> 3, c = (f & 7) << 2;
            *(float4*)&As[r * 32 + c] = pa[t];
            int kk = f >> 5, c2 = (f & 31) << 2;
            *(float4*)&Bs[kk * 128 + c2] = pb[t];
        }
        __syncthreads();
        if (k0 + 32 < 256) {
#pragma unroll
            for (int t = 0; t < 4; t++) {
                int f = tid + t * 256;
                int r = f >> 3, c = (f & 7) << 2;
                pa[t] = *(const float4*)&x[(row0 + r) * 256 + k0 + 32 + c];
                int kk = f >> 5, c2 = (f & 31) << 2;
                pb[t] = *(const float4*)&g_T1[(k0 + 32 + kk) * 128 + c2];
            }
        }
#pragma unroll 8
        for (int k = 0; k < 32; k++) {
            u64 aa[8], bb[4];
#pragma unroll
            for (int i = 0; i < 8; i++) {
                float av = As[(ty * 8 + i) * 32 + k];
                aa[i] = pack2(av, av);
            }
#pragma unroll
            for (int j = 0; j < 4; j++)
                bb[j] = *(const u64*)&Bs[k * 128 + j * 32 + tx * 2];
#pragma unroll
            for (int i = 0; i < 8; i++)
#pragma unroll
                for (int j = 0; j < 4; j++) fma2(acc[i][j], aa[i], bb[j]);
        }
    }
#pragma unroll
    for (int i = 0; i < 8; i++) {
        int r = row0 + ty * 8 + i;
#pragma unroll
        for (int j = 0; j < 4; j++)
            *(float2*)&g_U[r * 128 + j * 32 + tx * 2] = u2f(acc[i][j]);
    }
}

// ---------------- K2: forward stage 2 + even/odd combine ----------------
__global__ __launch_bounds__(256) void k_fwd2() {
    __shared__ float As[128 * 32];   // T2 slice [j][kk]
    __shared__ float Bs[32 * 128];   // U slice  [kk][j2]
    const int img = blockIdx.x;
    const float* Ub = &g_U[img * 256 * 128];
    const int tid = threadIdx.x;
    const int ty = tid >> 4, tx = tid & 15;
    const int s1b = ty * 4;

    float4 pa[4], pb[4];
#pragma unroll
    for (int t = 0; t < 4; t++) {
        int f = tid + t * 256;
        int j = f >> 3, c = (f & 7) << 2;
        pa[t] = *(const float4*)&g_T2[j * 256 + c];
        int kk = f >> 5, c2 = (f & 31) << 2;
        pb[t] = *(const float4*)&Ub[kk * 128 + c2];
    }
    u64 a00[4][2], a01[4][2], a10[4][2], a11[4][2];
#pragma unroll
    for (int i = 0; i < 4; i++)
#pragma unroll
        for (int j = 0; j < 2; j++) {
            a00[i][j] = 0ull; a01[i][j] = 0ull; a10[i][j] = 0ull; a11[i][j] = 0ull;
        }

    for (int m0 = 0; m0 < 256; m0 += 32) {
        __syncthreads();
#pragma unroll
        for (int t = 0; t < 4; t++) {
            int f = tid + t * 256;
            int j = f >> 3, c = (f & 7) << 2;
            *(float4*)&As[j * 32 + c] = pa[t];
            int kk = f >> 5, c2 = (f & 31) << 2;
            *(float4*)&Bs[kk * 128 + c2] = pb[t];
        }
        __syncthreads();
        if (m0 + 32 < 256) {
#pragma unroll
            for (int t = 0; t < 4; t++) {
                int f = tid + t * 256;
                int j = f >> 3, c = (f & 7) << 2;
                pa[t] = *(const float4*)&g_T2[j * 256 + m0 + 32 + c];
                int kk = f >> 5, c2 = (f & 31) << 2;
                pb[t] = *(const float4*)&Ub[(m0 + 32 + kk) * 128 + c2];
            }
        }
#pragma unroll 8
        for (int k = 0; k < 32; k++) {
            u64 aal[4], aah[4], bbl[2], bbh[2];
#pragma unroll
            for (int i = 0; i < 4; i++) {
                float al = As[(s1b + i) * 32 + k];
                float ah = As[(64 + s1b + i) * 32 + k];
                aal[i] = pack2(al, al);
                aah[i] = pack2(ah, ah);
            }
#pragma unroll
            for (int j = 0; j < 2; j++) {
                bbl[j] = *(const u64*)&Bs[k * 128 + j * 32 + tx * 2];
                bbh[j] = *(const u64*)&Bs[k * 128 + 64 + j * 32 + tx * 2];
            }
#pragma unroll
            for (int i = 0; i < 4; i++)
#pragma unroll
                for (int j = 0; j < 2; j++) {
                    fma2(a00[i][j], aal[i], bbl[j]);
                    fma2(a01[i][j], aal[i], bbh[j]);
                    fma2(a10[i][j], aah[i], bbl[j]);
                    fma2(a11[i][j], aah[i], bbh[j]);
                }
        }
    }
    // C = a00 - a11 ; S = a10 + a01. Layout: g_CS[comp][mode][ci*16 + b]
    const int b = img >> 6, ic = img & 63;
#pragma unroll
    for (int i = 0; i < 4; i++)
#pragma unroll
        for (int j = 0; j < 2; j++) {
            int s1 = s1b + i, s2 = j * 32 + tx * 2;
            float2 c0 = u2f(a00[i][j]), c1 = u2f(a11[i][j]);
            float2 s0 = u2f(a10[i][j]), s1v = u2f(a01[i][j]);
            int m0i = (s1 * 64 + s2) * 1024 + ic * 16 + b;
            g_CS[m0i] = c0.x - c1.x;
            g_CS[m0i + 1024] = c0.y - c1.y;
            g_CS[4096 * 1024 + m0i] = s0.x + s1v.x;
            g_CS[4096 * 1024 + m0i + 1024] = s0.y + s1v.y;
        }
}

// ---------------- K3: per-mode channel mixing ----------------
__global__ __launch_bounds__(256) void k_mix() {
    __shared__ float sC[1024], sS[1024];
    __shared__ float sW[4096], sWr[4096];
    const int mode = blockIdx.x;
    const int s1 = mode >> 6, s2 = mode & 63;
    const int f1 = (64 - s1) & 63, f2 = (64 - s2) & 63;
    const int tid = threadIdx.x;
    for (int t = tid; t < 1024; t += 256) {
        sC[t] = g_CS[mode * 1024 + t];
        sS[t] = g_CS[4096 * 1024 + mode * 1024 + t];
    }
    for (int t = tid; t < 4096; t += 256) {
        sW[t] = g_Wt[mode * 4096 + t];
        sWr[t] = g_Wt[(f1 * 64 + f2) * 4096 + t];
    }
    __syncthreads();
    const int o = tid & 63, bq = tid >> 6;
    u64 acc01 = 0ull, acc23 = 0ull;
#pragma unroll 8
    for (int i = 0; i < 64; i++) {
        float w = sW[i * 64 + o];
        float wr = sWr[i * 64 + o];
        u64 ww = pack2(w, w), wwr = pack2(wr, wr);
        u64 c01 = *(const u64*)&sC[i * 16 + bq * 4];
        u64 c23 = *(const u64*)&sC[i * 16 + bq * 4 + 2];
        u64 s01 = *(const u64*)&sS[i * 16 + bq * 4];
        u64 s23 = *(const u64*)&sS[i * 16 + bq * 4 + 2];
        fma2(acc01, c01, ww);
        fma2(acc01, s01, wwr);
        fma2(acc23, c23, ww);
        fma2(acc23, s23, wwr);
    }
    float2 v01 = u2f(acc01), v23 = u2f(acc23);
    g_Tt[((bq * 4 + 0) * 64 + o) * 4096 + mode] = v01.x;
    g_Tt[((bq * 4 + 1) * 64 + o) * 4096 + mode] = v01.y;
    g_Tt[((bq * 4 + 2) * 64 + o) * 4096 + mode] = v23.x;
    g_Tt[((bq * 4 + 3) * 64 + o) * 4096 + mode] = v23.y;
}

// ---------------- K4: inverse stage 1 ----------------
__global__ __launch_bounds__(256) void k_inv1() {
    __shared__ float As[64 * 64];    // Tot [s1][s2]
    __shared__ float Bs[64 * 128];   // T4 slice [s2][c]
    const int nh = blockIdx.x;
    const int img = blockIdx.y;
    const int tid = threadIdx.x;
#pragma unroll
    for (int t = 0; t < 4; t++) {
        int f = tid + t * 256;
        *(float4*)&As[f * 4] = *(const float4*)&g_Tt[img * 4096 + f * 4];
    }
#pragma unroll
    for (int t = 0; t < 8; t++) {
        int f = tid + t * 256;
        int s2 = f >> 5, c = (f & 31) << 2;
        *(float4*)&Bs[s2 * 128 + c] = *(const float4*)&g_T4[s2 * 512 + nh * 128 + c];
    }
    __syncthreads();
    const int ty = tid >> 5, tx = tid & 31;
    u64 acc[8][2];
#pragma unroll
    for (int i = 0; i < 8; i++) { acc[i][0] = 0ull; acc[i][1] = 0ull; }
#pragma unroll 8
    for (int k = 0; k < 64; k++) {
        u64 aa[8], bb[2];
#pragma unroll
        for (int i = 0; i < 8; i++) {
            float av = As[(ty * 8 + i) * 64 + k];
            aa[i] = pack2(av, av);
        }
        bb[0] = *(const u64*)&Bs[k * 128 + tx * 2];
        bb[1] = *(const u64*)&Bs[k * 128 + 64 + tx * 2];
#pragma unroll
        for (int i = 0; i < 8; i++) {
            fma2(acc[i][0], aa[i], bb[0]);
            fma2(acc[i][1], aa[i], bb[1]);
        }
    }
#pragma unroll
    for (int i = 0; i < 8; i++) {
        int s1 = ty * 8 + i;
#pragma unroll
        for (int jj = 0; jj < 2; jj++) {
            int col = nh * 128 + jj * 64 + tx * 2;
            int comp = col >> 8, n = col & 255;
            *(float2*)&g_V[((img * 64 + s1) * 2 + comp) * 256 + n] = u2f(acc[i][jj]);
        }
    }
}

// ---------------- K5: inverse stage 2 + bias + ReLU ----------------
__global__ __launch_bounds__(256) void k_inv2(const float* __restrict__ bias,
                                              float* __restrict__ out) {
    __shared__ float As[128 * 32];
    __shared__ float Bs[32 * 128];
    const int n0 = blockIdx.x * 128;
    const int m0 = blockIdx.y * 128;
    const int img = blockIdx.z;
    const float* Vb = &g_V[img * 128 * 256];
    const int tid = threadIdx.x;
    const int ty = tid >> 4, tx = tid & 15;

    float4 pa[4], pb[4];
#pragma unroll
    for (int t = 0; t < 4; t++) {
        int f = tid + t * 256;
        int r = f >> 3, c = (f & 7) << 2;
        pa[t] = *(const float4*)&g_A5[(m0 + r) * 128 + c];
        int kk = f >> 5, c2 = (f & 31) << 2;
        pb[t] = *(const float4*)&Vb[kk * 256 + n0 + c2];
    }
    u64 acc[8][4];
#pragma unroll
    for (int i = 0; i < 8; i++)
#pragma unroll
        for (int j = 0; j < 4; j++) acc[i][j] = 0ull;

    for (int k0 = 0; k0 < 128; k0 += 32) {
        __syncthreads();
#pragma unroll
        for (int t = 0; t < 4; t++) {
            int f = tid + t * 256;
            int r = f >> 3, c = (f & 7) << 2;
            *(float4*)&As[r * 32 + c] = pa[t];
            int kk = f >> 5, c2 = (f & 31) << 2;
            *(float4*)&Bs[kk * 128 + c2] = pb[t];
        }
        __syncthreads();
        if (k0 + 32 < 128) {
#pragma unroll
            for (int t = 0; t < 4; t++) {
                int f = tid + t * 256;
                int r = f >> 3, c = (f & 7) << 2;
                pa[t] = *(const float4*)&g_A5[(m0 + r) * 128 + k0 + 32 + c];
                int kk = f >> 5, c2 = (f & 31) << 2;
                pb[t] = *(const float4*)&Vb[(k0 + 32 + kk) * 256 + n0 + c2];
            }
        }
#pragma unroll 8
        for (int k = 0; k < 32; k++) {
            u64 aa[8], bb[4];
#pragma unroll
            for (int i = 0; i < 8; i++) {
                float av = As[(ty * 8 + i) * 32 + k];
                aa[i] = pack2(av, av);
            }
#pragma unroll
            for (int j = 0; j < 4; j++)
                bb[j] = *(const u64*)&Bs[k * 128 + j * 32 + tx * 2];
#pragma unroll
            for (int i = 0; i < 8; i++)
#pragma unroll
                for (int j = 0; j < 4; j++) fma2(acc[i][j], aa[i], bb[j]);
        }
    }
    const float bv = bias[img & 63];
    const float sc = 1.0f / 65536.0f;
#pragma unroll
    for (int i = 0; i < 8; i++) {
        int m = m0 + ty * 8 + i;
#pragma unroll
        for (int j = 0; j < 4; j++) {
            float2 v = u2f(acc[i][j]);
            v.x = fmaxf(fmaf(v.x, sc, bv), 0.f);
            v.y = fmaxf(fmaf(v.y, sc, bv), 0.f);
            *(float2*)&out[(img * 256 + m) * 256 + n0 + j * 32 + tx * 2] = v;
        }
    }
}

extern "C" void kernel_launch(void* const* d_in, const int* in_sizes, int n_in,
                              void* d_out, int out_size) {
    const float* x = (const float*)d_in[0];     // [16,64,256,256]
    const float* w = (const float*)d_in[1];     // [64,64,64,64]
    const float* bias = (const float*)d_in[2];  // [64]
    float* out = (float*)d_out;                 // [16,64,256,256]

    k_tables<<<256, 128>>>();
    k_wt<<<dim3(128, 128), dim3(32, 8)>>>(w);
    k_fwd1<<<2048, 256>>>(x);
    k_fwd2<<<1024, 256>>>();
    k_mix<<<4096, 256>>>();
    k_inv1<<<dim3(4, 1024), 256>>>();
    k_inv2<<<dim3(2, 2, 1024), 256>>>(bias, out);
}

// round 6
// speedup vs baseline: 1.2285x; 1.2285x over previous
#include <cuda_runtime.h>
#include <cuda_bf16.h>
#include <cstdint>

// HartleySpectralConv2d B=16,CI=CO=64,H=W=256, modes 64x64.
// Split-bf16 (3-term) GEMMs on mma.sync.m16n8k16 (HMMA), fp32 accum.
// K1: Ut[img][j][m] = sum_n Tc[j,n]*x[m,n]
// K2: R[j][j2]      = sum_m Tc[j,m]*Ut[j2,m]  -> combine -> CS
// K3: k_mix (fp32)  -> Tot split bf16 [img][s2*64+s1]
// K4: W[(c,m)][s2]  = sum_s1 A5[c][m,s1]*Tot[s1,s2]
// K5: out[m][n]     = (sum_k W[m,k]*T5[n,k])/65536 + bias, ReLU

using bf16 = __nv_bfloat16;
using u32 = uint32_t; using ull = unsigned long long;

__device__ bf16 g_Tch[128 * 256], g_Tcl[128 * 256];     // [j][n] K-major
__device__ bf16 g_A5h[2 * 256 * 64], g_A5l[2 * 256 * 64]; // [(c*256+m)][s1]
__device__ bf16 g_T5h[256 * 128], g_T5l[256 * 128];     // [n][c*64+s2]
__device__ bf16 g_Xh[67108864], g_Xl[67108864];         // [row][n]  (16*64*256 rows)
__device__ bf16 g_Uth[1024 * 128 * 256], g_Utl[1024 * 128 * 256]; // [img][j][m]
__device__ float g_Wt[4096 * 4096];                     // [mode][i*64+o]
__device__ float g_CS[2 * 4096 * 1024];                 // [comp][mode][ci*16+b]
__device__ bf16 g_Tth[1024 * 4096], g_Ttl[1024 * 4096]; // [img][s2*64+s1]
__device__ bf16 g_Wh[1024 * 256 * 128], g_Wl[1024 * 256 * 128]; // [img][m][k]

// ---------------- helpers ----------------
__device__ __forceinline__ u32 smem_u32(const void* p) {
    u32 a;
    asm("{ .reg .u64 t; cvta.to.shared.u64 t, %1; cvt.u32.u64 %0, t; }" : "=r"(a) : "l"(p));
    return a;
}
__device__ __forceinline__ void ldsm4(u32* r, u32 a) {
    asm volatile("ldmatrix.sync.aligned.m8n8.x4.shared.b16 {%0,%1,%2,%3}, [%4];"
                 : "=r"(r[0]), "=r"(r[1]), "=r"(r[2]), "=r"(r[3]) : "r"(a));
}
__device__ __forceinline__ void mmabf(float* d, const u32* a, const u32* b) {
    asm volatile("mma.sync.aligned.m16n8k16.row.col.f32.bf16.bf16.f32 "
                 "{%0,%1,%2,%3}, {%4,%5,%6,%7}, {%8,%9}, {%0,%1,%2,%3};"
                 : "+f"(d[0]), "+f"(d[1]), "+f"(d[2]), "+f"(d[3])
                 : "r"(a[0]), "r"(a[1]), "r"(a[2]), "r"(a[3]), "r"(b[0]), "r"(b[1]));
}
__device__ __forceinline__ u32 pack_bf(bf16 a, bf16 b) {
    return (u32)__bfloat16_as_ushort(a) | ((u32)__bfloat16_as_ushort(b) << 16);
}
__device__ __forceinline__ void bsplit(float v, bf16& h, bf16& l) {
    h = __float2bfloat16(v);
    l = __float2bfloat16(v - __bfloat162float(h));
}
__device__ __forceinline__ u32 pack_h(float a, float b) {
    bf16 h0, l0, h1, l1; bsplit(a, h0, l0); bsplit(b, h1, l1); return pack_bf(h0, h1);
}
__device__ __forceinline__ u32 pack_l(float a, float b) {
    bf16 h0, l0, h1, l1; bsplit(a, h0, l0); bsplit(b, h1, l1); return pack_bf(l0, l1);
}

// tile: 128 rows x 32 bf16 cols, smem row stride 40 (80B, conflict-free)
__device__ __forceinline__ void ld2(uint4* r, const bf16* __restrict__ src, int ld, int k0, int tid) {
#pragma unroll
    for (int t = 0; t < 2; t++) {
        int f = tid + t * 256, row = f >> 2, c = f & 3;
        r[t] = *(const uint4*)&src[row * ld + k0 + c * 8];
    }
}
__device__ __forceinline__ void st2(char* smem, int off, const uint4* r, int tid) {
#pragma unroll
    for (int t = 0; t < 2; t++) {
        int f = tid + t * 256, row = f >> 2, c = f & 3;
        *(uint4*)(smem + off + (row * 40 + c * 8) * 2) = r[t];
    }
}
// warp tile 32(m) x 64(n), K-chunk 32
__device__ __forceinline__ void wchunk(float c[2][8][4], u32 sA, u32 sB, int lane, int wy, int wx) {
    int rowA = wy * 32 + (lane & 15);
    int colA = (lane >> 4) * 8;
    int rowB = wx * 64 + (lane & 7) + ((lane >> 4) << 3);
    int colB = ((lane >> 3) & 1) * 8;
#pragma unroll
    for (int kk = 0; kk < 32; kk += 16) {
        u32 a[2][4], b[4][4];
#pragma unroll
        for (int mi = 0; mi < 2; mi++)
            ldsm4(a[mi], sA + ((rowA + mi * 16) * 40 + kk + colA) * 2);
#pragma unroll
        for (int np = 0; np < 4; np++)
            ldsm4(b[np], sB + ((rowB + np * 16) * 40 + kk + colB) * 2);
#pragma unroll
        for (int mi = 0; mi < 2; mi++)
#pragma unroll
            for (int ni = 0; ni < 8; ni++)
                mmabf(c[mi][ni], a[mi], &b[ni >> 1][(ni & 1) * 2]);
    }
}
// mainloop: block 128x128, 3 segments, KSEG chunks each
template <int KSEG>
__device__ __forceinline__ void gmain(const bf16* A0, const bf16* A1, const bf16* A2,
                                      const bf16* B0, const bf16* B1, const bf16* B2,
                                      int lda, int ldb, float c[2][8][4],
                                      char* smem, u32 sb, int tid, int lane, int wy, int wx) {
    const bf16* As[3] = {A0, A1, A2};
    const bf16* Bs[3] = {B0, B1, B2};
    const int NCH = 3 * KSEG;
    uint4 pa[2], pb[2];
    ld2(pa, As[0], lda, 0, tid);
    ld2(pb, Bs[0], ldb, 0, tid);
    st2(smem, 0, pa, tid);
    st2(smem, 10240, pb, tid);
    __syncthreads();
    for (int ch = 0; ch < NCH; ch++) {
        if (ch + 1 < NCH) {
            int seg = (ch + 1) / KSEG, k0 = ((ch + 1) % KSEG) * 32;
            ld2(pa, As[seg], lda, k0, tid);
            ld2(pb, Bs[seg], ldb, k0, tid);
        }
        u32 sA = sb + (ch & 1) * 20480;
        wchunk(c, sA, sA + 10240, lane, wy, wx);
        if (ch + 1 < NCH) {
            int o = ((ch + 1) & 1) * 20480;
            st2(smem, o, pa, tid);
            st2(smem, o + 10240, pb, tid);
            __syncthreads();
        }
    }
}

// ---------------- K0: split trig tables ----------------
__global__ void k_tables() {
    int a = blockIdx.x, b = threadIdx.x;
    int s = b & 63, k = s - 32;
    int q = ((k * a) % 256 + 256) % 256;
    float sv, cv;
    sincospif((float)q * (1.0f / 128.0f), &sv, &cv);
    float tc = (b < 64) ? cv : sv;
    bf16 h, l;
    bsplit(tc, h, l);
    g_Tch[b * 256 + a] = h; g_Tcl[b * 256 + a] = l;
    g_T5h[a * 128 + b] = h; g_T5l[a * 128 + b] = l;
    int c = b >> 6;
    float a5 = c ? (cv - sv) : (cv + sv);
    bsplit(a5, h, l);
    g_A5h[(c * 256 + a) * 64 + s] = h;
    g_A5l[(c * 256 + a) * 64 + s] = l;
}

// ---------------- split x ----------------
__global__ __launch_bounds__(256) void k_split(const float* __restrict__ x) {
    int i = (blockIdx.x * 256 + threadIdx.x) * 4;
    float4 v = *(const float4*)&x[i];
    uint2 hh = make_uint2(pack_h(v.x, v.y), pack_h(v.z, v.w));
    uint2 ll = make_uint2(pack_l(v.x, v.y), pack_l(v.z, v.w));
    *(uint2*)&g_Xh[i] = hh;
    *(uint2*)&g_Xl[i] = ll;
}

// ---------------- Kw: weight transpose ----------------
__global__ void k_wt(const float* __restrict__ w) {
    __shared__ float tile[32][33];
    int x0 = blockIdx.x * 32, y0 = blockIdx.y * 32;
    int tx = threadIdx.x, ty = threadIdx.y;
#pragma unroll
    for (int r = 0; r < 32; r += 8)
        tile[ty + r][tx] = w[(y0 + ty + r) * 4096 + x0 + tx];
    __syncthreads();
#pragma unroll
    for (int r = 0; r < 32; r += 8)
        g_Wt[(x0 + ty + r) * 4096 + y0 + tx] = tile[tx][ty + r];
}

// ---------------- K1 ----------------
__global__ __launch_bounds__(256) void k1_fwd() {
    extern __shared__ char smem[];
    u32 sb = smem_u32(smem);
    int tid = threadIdx.x, lane = tid & 31, w = tid >> 5, wy = w >> 1, wx = w & 1;
    int mt = blockIdx.x, img = mt >> 1, mh = mt & 1, row0 = mt * 128;
    float c[2][8][4];
#pragma unroll
    for (int i = 0; i < 2; i++)
#pragma unroll
        for (int j = 0; j < 8; j++)
#pragma unroll
            for (int r = 0; r < 4; r++) c[i][j][r] = 0.f;
    gmain<8>(g_Tch, g_Tch, g_Tcl,
             g_Xh + (long long)row0 * 256, g_Xl + (long long)row0 * 256, g_Xh + (long long)row0 * 256,
             256, 256, c, smem, sb, tid, lane, wy, wx);
    int g = lane >> 2, cp = (lane & 3) * 2;
#pragma unroll
    for (int mi = 0; mi < 2; mi++)
#pragma unroll
        for (int ni = 0; ni < 8; ni++) {
            int col = mh * 128 + wx * 64 + ni * 8 + cp;
            int r0 = wy * 32 + mi * 16 + g;
            int b0 = (img * 128 + r0) * 256 + col;
            int b1 = b0 + 8 * 256;
            float* d = c[mi][ni];
            *(u32*)&g_Uth[b0] = pack_h(d[0], d[1]);
            *(u32*)&g_Utl[b0] = pack_l(d[0], d[1]);
            *(u32*)&g_Uth[b1] = pack_h(d[2], d[3]);
            *(u32*)&g_Utl[b1] = pack_l(d[2], d[3]);
        }
}

// ---------------- K2 ----------------
__global__ __launch_bounds__(256) void k2_fwd() {
    extern __shared__ char smem[];
    u32 sb = smem_u32(smem);
    int tid = threadIdx.x, lane = tid & 31, w = tid >> 5, wy = w >> 1, wx = w & 1;
    int img = blockIdx.x;
    const bf16* Uh = g_Uth + img * 32768;
    const bf16* Ul = g_Utl + img * 32768;
    float c[2][8][4];
#pragma unroll
    for (int i = 0; i < 2; i++)
#pragma unroll
        for (int j = 0; j < 8; j++)
#pragma unroll
            for (int r = 0; r < 4; r++) c[i][j][r] = 0.f;
    gmain<8>(g_Tch, g_Tch, g_Tcl, Uh, Ul, Uh, 256, 256, c, smem, sb, tid, lane, wy, wx);
    // stage R into smem fp32 [128][132]
    float* F = (float*)(smem + 40960);
    int g = lane >> 2, cp = (lane & 3) * 2;
#pragma unroll
    for (int mi = 0; mi < 2; mi++)
#pragma unroll
        for (int ni = 0; ni < 8; ni++) {
            int col = wx * 64 + ni * 8 + cp;
            int r0 = wy * 32 + mi * 16 + g;
            float* d = c[mi][ni];
            F[r0 * 132 + col] = d[0];
            F[r0 * 132 + col + 1] = d[1];
            F[(r0 + 8) * 132 + col] = d[2];
            F[(r0 + 8) * 132 + col + 1] = d[3];
        }
    __syncthreads();
    const int b = img >> 6, ic = img & 63;
#pragma unroll
    for (int t = 0; t < 16; t++) {
        int p = tid + t * 256;
        int s1 = p >> 6, s2 = p & 63;
        float r00 = F[s1 * 132 + s2];
        float r01 = F[s1 * 132 + 64 + s2];
        float r10 = F[(64 + s1) * 132 + s2];
        float r11 = F[(64 + s1) * 132 + 64 + s2];
        int a = p * 1024 + ic * 16 + b;
        g_CS[a] = r00 - r11;
        g_CS[4194304 + a] = r10 + r01;
    }
}

// ---------------- K3: channel mixing (fp32) ----------------
__device__ __forceinline__ ull pk2(float lo, float hi) {
    ull r; asm("mov.b64 %0, {%1, %2};" : "=l"(r) : "f"(lo), "f"(hi)); return r;
}
__device__ __forceinline__ float2 up2(ull v) {
    float2 f; asm("mov.b64 {%0, %1}, %2;" : "=f"(f.x), "=f"(f.y) : "l"(v)); return f;
}
__device__ __forceinline__ void fm2(ull& d, ull a, ull b) {
    asm("fma.rn.f32x2 %0, %1, %2, %0;" : "+l"(d) : "l"(a), "l"(b));
}
__global__ __launch_bounds__(256) void k_mix() {
    __shared__ float sC[1024], sS[1024];
    __shared__ float sW[4096], sWr[4096];
    const int mode = blockIdx.x;
    const int s1 = mode >> 6, s2 = mode & 63;
    const int f1 = (64 - s1) & 63, f2 = (64 - s2) & 63;
    const int tid = threadIdx.x;
    for (int t = tid; t < 1024; t += 256) {
        sC[t] = g_CS[mode * 1024 + t];
        sS[t] = g_CS[4194304 + mode * 1024 + t];
    }
    for (int t = tid; t < 4096; t += 256) {
        sW[t] = g_Wt[mode * 4096 + t];
        sWr[t] = g_Wt[(f1 * 64 + f2) * 4096 + t];
    }
    __syncthreads();
    const int o = tid & 63, bq = tid >> 6;
    ull acc01 = 0ull, acc23 = 0ull;
#pragma unroll 8
    for (int i = 0; i < 64; i++) {
        float wv = sW[i * 64 + o];
        float wr = sWr[i * 64 + o];
        ull ww = pk2(wv, wv), wwr = pk2(wr, wr);
        fm2(acc01, *(const ull*)&sC[i * 16 + bq * 4], ww);
        fm2(acc01, *(const ull*)&sS[i * 16 + bq * 4], wwr);
        fm2(acc23, *(const ull*)&sC[i * 16 + bq * 4 + 2], ww);
        fm2(acc23, *(const ull*)&sS[i * 16 + bq * 4 + 2], wwr);
    }
    float2 v01 = up2(acc01), v23 = up2(acc23);
    float vals[4] = {v01.x, v01.y, v23.x, v23.y};
#pragma unroll
    for (int r = 0; r < 4; r++) {
        int img2 = (bq * 4 + r) * 64 + o;
        bf16 h, l;
        bsplit(vals[r], h, l);
        g_Tth[img2 * 4096 + s2 * 64 + s1] = h;
        g_Ttl[img2 * 4096 + s2 * 64 + s1] = l;
    }
}

// ---------------- K4: M=256 (c,m), N=64, K=64, 3 segs ----------------
__global__ __launch_bounds__(256) void k4_inv() {
    extern __shared__ char smem[];
    u32 sb = smem_u32(smem);
    int tid = threadIdx.x, lane = tid & 31, w = tid >> 5, wy = w >> 1, wx = w & 1;
    int img = blockIdx.x >> 1, m0 = (blockIdx.x & 1) * 128;
    const bf16* As[3] = {g_A5h, g_A5h, g_A5l};
    const bf16* Bs[3] = {g_Tth + img * 4096, g_Ttl + img * 4096, g_Tth + img * 4096};
    // A tile 256x32 (stride 40, 20480B); B tile 64x32 (5120B)
    const int ASZ = 20480, BUF = ASZ + 5120;
    float c[4][4][4];
#pragma unroll
    for (int i = 0; i < 4; i++)
#pragma unroll
        for (int j = 0; j < 4; j++)
#pragma unroll
            for (int r = 0; r < 4; r++) c[i][j][r] = 0.f;
    uint4 pa[4], pb;
    {
#pragma unroll
        for (int t = 0; t < 4; t++) {
            int f = tid + t * 256, row = f >> 2, cc = f & 3;
            int gr = (row < 128) ? (m0 + row) : (256 + m0 + row - 128);
            pa[t] = *(const uint4*)&As[0][gr * 64 + cc * 8];
        }
        int row = tid >> 2, cc = tid & 3;
        pb = *(const uint4*)&Bs[0][row * 64 + cc * 8];
#pragma unroll
        for (int t = 0; t < 4; t++) {
            int f = tid + t * 256, row2 = f >> 2, c2 = f & 3;
            *(uint4*)(smem + (row2 * 40 + c2 * 8) * 2) = pa[t];
        }
        *(uint4*)(smem + ASZ + (row * 40 + cc * 8) * 2) = pb;
    }
    __syncthreads();
    const int NCH = 6;
    for (int ch = 0; ch < NCH; ch++) {
        if (ch + 1 < NCH) {
            int seg = (ch + 1) / 2, k0 = ((ch + 1) % 2) * 32;
#pragma unroll
            for (int t = 0; t < 4; t++) {
                int f = tid + t * 256, row = f >> 2, cc = f & 3;
                int gr = (row < 128) ? (m0 + row) : (256 + m0 + row - 128);
                pa[t] = *(const uint4*)&As[seg][gr * 64 + k0 + cc * 8];
            }
            int row = tid >> 2, cc = tid & 3;
            pb = *(const uint4*)&Bs[seg][row * 64 + k0 + cc * 8];
        }
        // compute: warp tile 64x32
        {
            u32 sA = sb + (ch & 1) * BUF, sB = sA + ASZ;
            int rowA = wy * 64 + (lane & 15);
            int colA = (lane >> 4) * 8;
            int rowB = wx * 32 + (lane & 7) + ((lane >> 4) << 3);
            int colB = ((lane >> 3) & 1) * 8;
#pragma unroll
            for (int kk = 0; kk < 32; kk += 16) {
                u32 a[4][4], b[2][4];
#pragma unroll
                for (int mi = 0; mi < 4; mi++)
                    ldsm4(a[mi], sA + ((rowA + mi * 16) * 40 + kk + colA) * 2);
#pragma unroll
                for (int np = 0; np < 2; np++)
                    ldsm4(b[np], sB + ((rowB + np * 16) * 40 + kk + colB) * 2);
#pragma unroll
                for (int mi = 0; mi < 4; mi++)
#pragma unroll
                    for (int ni = 0; ni < 4; ni++)
                        mmabf(c[mi][ni], a[mi], &b[ni >> 1][(ni & 1) * 2]);
            }
        }
        if (ch + 1 < NCH) {
            int o = ((ch + 1) & 1) * BUF;
#pragma unroll
            for (int t = 0; t < 4; t++) {
                int f = tid + t * 256, row = f >> 2, cc = f & 3;
                *(uint4*)(smem + o + (row * 40 + cc * 8) * 2) = pa[t];
            }
            int row = tid >> 2, cc = tid & 3;
            *(uint4*)(smem + o + ASZ + (row * 40 + cc * 8) * 2) = pb;
            __syncthreads();
        }
    }
    int g = lane >> 2, cp = (lane & 3) * 2;
#pragma unroll
    for (int mi = 0; mi < 4; mi++)
#pragma unroll
        for (int ni = 0; ni < 4; ni++) {
            int s2 = wx * 32 + ni * 8 + cp;
            float* d = c[mi][ni];
#pragma unroll
            for (int half = 0; half < 2; half++) {
                int rL = wy * 64 + mi * 16 + g + half * 8;
                int cc = rL >> 7, m = m0 + (rL & 127);
                int idx = (img * 256 + m) * 128 + cc * 64 + s2;
                *(u32*)&g_Wh[idx] = pack_h(d[half * 2], d[half * 2 + 1]);
                *(u32*)&g_Wl[idx] = pack_l(d[half * 2], d[half * 2 + 1]);
            }
        }
}

// ---------------- K5 ----------------
__global__ __launch_bounds__(256) void k5_inv(const float* __restrict__ bias,
                                              float* __restrict__ out) {
    extern __shared__ char smem[];
    u32 sb = smem_u32(smem);
    int tid = threadIdx.x, lane = tid & 31, w = tid >> 5, wy = w >> 1, wx = w & 1;
    int n0 = blockIdx.x * 128, m0 = blockIdx.y * 128, img = blockIdx.z;
    const bf16* Ah = g_Wh + (img * 256 + m0) * 128;
    const bf16* Al = g_Wl + (img * 256 + m0) * 128;
    float c[2][8][4];
#pragma unroll
    for (int i = 0; i < 2; i++)
#pragma unroll
        for (int j = 0; j < 8; j++)
#pragma unroll
            for (int r = 0; r < 4; r++) c[i][j][r] = 0.f;
    gmain<4>(Ah, Ah, Al,
             g_T5h + n0 * 128, g_T5l + n0 * 128, g_T5h + n0 * 128,
             128, 128, c, smem, sb, tid, lane, wy, wx);
    const float bv = bias[img & 63];
    const float sc = 1.0f / 65536.0f;
    int g = lane >> 2, cp = (lane & 3) * 2;
#pragma unroll
    for (int mi = 0; mi < 2; mi++)
#pragma unroll
        for (int ni = 0; ni < 8; ni++) {
            int col = n0 + wx * 64 + ni * 8 + cp;
            float* d = c[mi][ni];
#pragma unroll
            for (int half = 0; half < 2; half++) {
                int m = m0 + wy * 32 + mi * 16 + g + half * 8;
                float2 v;
                v.x = fmaxf(fmaf(d[half * 2], sc, bv), 0.f);
                v.y = fmaxf(fmaf(d[half * 2 + 1], sc, bv), 0.f);
                *(float2*)&out[(img * 256 + m) * 256 + col] = v;
            }
        }
}

extern "C" void kernel_launch(void* const* d_in, const int* in_sizes, int n_in,
                              void* d_out, int out_size) {
    const float* x = (const float*)d_in[0];
    const float* wgt = (const float*)d_in[1];
    const float* bias = (const float*)d_in[2];
    float* out = (float*)d_out;

    cudaFuncSetAttribute(k2_fwd, cudaFuncAttributeMaxDynamicSharedMemorySize, 108544);
    cudaFuncSetAttribute(k4_inv, cudaFuncAttributeMaxDynamicSharedMemorySize, 51200);

    k_tables<<<256, 128>>>();
    k_split<<<65536, 256>>>(x);
    k_wt<<<dim3(128, 128), dim3(32, 8)>>>(wgt);
    k1_fwd<<<2048, 256, 40960>>>();
    k2_fwd<<<1024, 256, 108544>>>();
    k_mix<<<4096, 256>>>();
    k4_inv<<<2048, 256, 51200>>>();
    k5_inv<<<dim3(2, 2, 1024), 256, 40960>>>(bias, out);
}

// round 7
// speedup vs baseline: 1.3872x; 1.1293x over previous
#include <cuda_runtime.h>
#include <cuda_bf16.h>
#include <cstdint>

// HartleySpectralConv2d B=16,CI=CO=64,H=W=256, modes 64x64.
// Split-bf16 GEMMs on mma.sync.m16n8k16 (HMMA), fp32 accum.
// Interleaved h/l: per k-chunk load Ah,Al,Bh,Bl once; acc += AhBh+AhBl+AlBh.
// K1: Ut[img][j][m] = sum_n Tc[j,n]*x[m,n]   (x split in-kernel)
// K2: R[j][j2]      = sum_m Tc[j,m]*Ut[j2,m] -> combine -> CS
// K3: k_mix (fp32)  -> Tot split bf16 [img][s2*64+s1]
// K4: W[(c,m)][s2]  = sum_s1 A5[c][m,s1]*Tot[s1,s2]
// K5: out[m][n]     = (sum_k W[m,k]*T5[n,k])/65536 + bias, ReLU

using bf16 = __nv_bfloat16;
using u32 = uint32_t; using ull = unsigned long long;

__device__ bf16 g_Tch[128 * 256], g_Tcl[128 * 256];       // [j][n] K-major
__device__ bf16 g_A5h[2 * 256 * 64], g_A5l[2 * 256 * 64]; // [(c*256+m)][s1]
__device__ bf16 g_T5h[256 * 128], g_T5l[256 * 128];       // [n][c*64+s2]
__device__ bf16 g_Uth[1024 * 128 * 256], g_Utl[1024 * 128 * 256]; // [img][j][m]
__device__ float g_Wt[4096 * 4096];                       // [mode][i*64+o]
__device__ float g_CS[2 * 4096 * 1024];                   // [comp][mode][ci*16+b]
__device__ bf16 g_Tth[1024 * 4096], g_Ttl[1024 * 4096];   // [img][s2*64+s1]
__device__ bf16 g_Wh[1024 * 256 * 128], g_Wl[1024 * 256 * 128]; // [img][m][k]

// ---------------- helpers ----------------
__device__ __forceinline__ u32 smem_u32(const void* p) {
    u32 a;
    asm("{ .reg .u64 t; cvta.to.shared.u64 t, %1; cvt.u32.u64 %0, t; }" : "=r"(a) : "l"(p));
    return a;
}
__device__ __forceinline__ void ldsm4(u32* r, u32 a) {
    asm volatile("ldmatrix.sync.aligned.m8n8.x4.shared.b16 {%0,%1,%2,%3}, [%4];"
                 : "=r"(r[0]), "=r"(r[1]), "=r"(r[2]), "=r"(r[3]) : "r"(a));
}
__device__ __forceinline__ void mmabf(float* d, const u32* a, const u32* b) {
    asm volatile("mma.sync.aligned.m16n8k16.row.col.f32.bf16.bf16.f32 "
                 "{%0,%1,%2,%3}, {%4,%5,%6,%7}, {%8,%9}, {%0,%1,%2,%3};"
                 : "+f"(d[0]), "+f"(d[1]), "+f"(d[2]), "+f"(d[3])
                 : "r"(a[0]), "r"(a[1]), "r"(a[2]), "r"(a[3]), "r"(b[0]), "r"(b[1]));
}
__device__ __forceinline__ u32 pack_bf(bf16 a, bf16 b) {
    return (u32)__bfloat16_as_ushort(a) | ((u32)__bfloat16_as_ushort(b) << 16);
}
__device__ __forceinline__ void bsplit(float v, bf16& h, bf16& l) {
    h = __float2bfloat16(v);
    l = __float2bfloat16(v - __bfloat162float(h));
}
__device__ __forceinline__ u32 pack_h(float a, float b) {
    bf16 h0, l0, h1, l1; bsplit(a, h0, l0); bsplit(b, h1, l1); return pack_bf(h0, h1);
}
__device__ __forceinline__ u32 pack_l(float a, float b) {
    bf16 h0, l0, h1, l1; bsplit(a, h0, l0); bsplit(b, h1, l1); return pack_bf(l0, l1);
}

// tile: 128 rows x 32 bf16 cols, smem row stride 40 elems (80B)
__device__ __forceinline__ void ld2(uint4* r, const bf16* __restrict__ src, int ld, int k0, int tid) {
#pragma unroll
    for (int t = 0; t < 2; t++) {
        int f = tid + t * 256, row = f >> 2, c = f & 3;
        r[t] = *(const uint4*)&src[(long long)row * ld + k0 + c * 8];
    }
}
__device__ __forceinline__ void st2(char* smem, int off, const uint4* r, int tid) {
#pragma unroll
    for (int t = 0; t < 2; t++) {
        int f = tid + t * 256, row = f >> 2, c = f & 3;
        *(uint4*)(smem + off + (row * 40 + c * 8) * 2) = r[t];
    }
}
// Buffer layout (per 40960B buffer): Ah@0, Al@10240, Bh@20480, Bl@30720
// warp tile 32(m) x 64(n), k-chunk 32; 3 terms per fragment load
__device__ __forceinline__ void wchunk_hl(float c[2][8][4], u32 base, int lane, int wy, int wx) {
    int rowA = wy * 32 + (lane & 15);
    int colA = (lane >> 4) * 8;
    int rowB = wx * 64 + (lane & 7) + ((lane >> 4) << 3);
    int colB = ((lane >> 3) & 1) * 8;
#pragma unroll
    for (int kk = 0; kk < 32; kk += 16) {
        u32 ah[2][4], al[2][4], bh[4][4], bl[4][4];
#pragma unroll
        for (int mi = 0; mi < 2; mi++) {
            u32 ao = ((rowA + mi * 16) * 40 + kk + colA) * 2;
            ldsm4(ah[mi], base + ao);
            ldsm4(al[mi], base + 10240 + ao);
        }
#pragma unroll
        for (int np = 0; np < 4; np++) {
            u32 bo = ((rowB + np * 16) * 40 + kk + colB) * 2;
            ldsm4(bh[np], base + 20480 + bo);
            ldsm4(bl[np], base + 30720 + bo);
        }
#pragma unroll
        for (int mi = 0; mi < 2; mi++)
#pragma unroll
            for (int ni = 0; ni < 8; ni++)
                mmabf(c[mi][ni], ah[mi], &bh[ni >> 1][(ni & 1) * 2]);
#pragma unroll
        for (int mi = 0; mi < 2; mi++)
#pragma unroll
            for (int ni = 0; ni < 8; ni++)
                mmabf(c[mi][ni], ah[mi], &bl[ni >> 1][(ni & 1) * 2]);
#pragma unroll
        for (int mi = 0; mi < 2; mi++)
#pragma unroll
            for (int ni = 0; ni < 8; ni++)
                mmabf(c[mi][ni], al[mi], &bh[ni >> 1][(ni & 1) * 2]);
    }
}
// generic h/l mainloop: A,B both bf16 h/l pairs
template <int NCH>
__device__ __forceinline__ void gmain_hl(const bf16* Ah, const bf16* Al,
                                         const bf16* Bh, const bf16* Bl,
                                         int lda, int ldb, float c[2][8][4],
                                         char* smem, u32 sb, int tid, int lane, int wy, int wx) {
    uint4 pah[2], pal[2], pbh[2], pbl[2];
    ld2(pah, Ah, lda, 0, tid); ld2(pal, Al, lda, 0, tid);
    ld2(pbh, Bh, ldb, 0, tid); ld2(pbl, Bl, ldb, 0, tid);
    st2(smem, 0, pah, tid); st2(smem, 10240, pal, tid);
    st2(smem, 20480, pbh, tid); st2(smem, 30720, pbl, tid);
    __syncthreads();
    for (int ch = 0; ch < NCH; ch++) {
        if (ch + 1 < NCH) {
            int k0 = (ch + 1) * 32;
            ld2(pah, Ah, lda, k0, tid); ld2(pal, Al, lda, k0, tid);
            ld2(pbh, Bh, ldb, k0, tid); ld2(pbl, Bl, ldb, k0, tid);
        }
        wchunk_hl(c, sb + (ch & 1) * 40960, lane, wy, wx);
        if (ch + 1 < NCH) {
            int o = ((ch + 1) & 1) * 40960;
            st2(smem, o, pah, tid); st2(smem, o + 10240, pal, tid);
            st2(smem, o + 20480, pbh, tid); st2(smem, o + 30720, pbl, tid);
            __syncthreads();
        }
    }
}

// ---------------- K0: split trig tables ----------------
__global__ void k_tables() {
    int a = blockIdx.x, b = threadIdx.x;
    int s = b & 63, k = s - 32;
    int q = ((k * a) % 256 + 256) % 256;
    float sv, cv;
    sincospif((float)q * (1.0f / 128.0f), &sv, &cv);
    float tc = (b < 64) ? cv : sv;
    bf16 h, l;
    bsplit(tc, h, l);
    g_Tch[b * 256 + a] = h; g_Tcl[b * 256 + a] = l;
    g_T5h[a * 128 + b] = h; g_T5l[a * 128 + b] = l;
    int c = b >> 6;
    float a5 = c ? (cv - sv) : (cv + sv);
    bsplit(a5, h, l);
    g_A5h[(c * 256 + a) * 64 + s] = h;
    g_A5l[(c * 256 + a) * 64 + s] = l;
}

// ---------------- Kw: weight transpose ----------------
__global__ void k_wt(const float* __restrict__ w) {
    __shared__ float tile[32][33];
    int x0 = blockIdx.x * 32, y0 = blockIdx.y * 32;
    int tx = threadIdx.x, ty = threadIdx.y;
#pragma unroll
    for (int r = 0; r < 32; r += 8)
        tile[ty + r][tx] = w[(y0 + ty + r) * 4096 + x0 + tx];
    __syncthreads();
#pragma unroll
    for (int r = 0; r < 32; r += 8)
        g_Wt[(x0 + ty + r) * 4096 + y0 + tx] = tile[tx][ty + r];
}

// ---------------- K1 (x split fused in tile load) ----------------
__global__ __launch_bounds__(256) void k1_fwd(const float* __restrict__ x) {
    extern __shared__ char smem[];
    u32 sb = smem_u32(smem);
    int tid = threadIdx.x, lane = tid & 31, w = tid >> 5, wy = w >> 1, wx = w & 1;
    int mt = blockIdx.x, img = mt >> 1, mh = mt & 1;
    const float* xb = x + (long long)mt * 128 * 256;
    float c[2][8][4];
#pragma unroll
    for (int i = 0; i < 2; i++)
#pragma unroll
        for (int j = 0; j < 8; j++)
#pragma unroll
            for (int r = 0; r < 4; r++) c[i][j][r] = 0.f;

    uint4 pah[2], pal[2];
    float4 px[4];
    ld2(pah, g_Tch, 256, 0, tid);
    ld2(pal, g_Tcl, 256, 0, tid);
#pragma unroll
    for (int t = 0; t < 4; t++) {
        int f = tid + t * 256, row = f >> 3, c4 = f & 7;
        px[t] = *(const float4*)&xb[row * 256 + c4 * 4];
    }
    st2(smem, 0, pah, tid);
    st2(smem, 10240, pal, tid);
#pragma unroll
    for (int t = 0; t < 4; t++) {
        int f = tid + t * 256, row = f >> 3, c4 = f & 7;
        int off = (row * 40 + c4 * 4) * 2;
        float4 v = px[t];
        *(uint2*)(smem + 20480 + off) = make_uint2(pack_h(v.x, v.y), pack_h(v.z, v.w));
        *(uint2*)(smem + 30720 + off) = make_uint2(pack_l(v.x, v.y), pack_l(v.z, v.w));
    }
    __syncthreads();
    const int NCH = 8;
    for (int ch = 0; ch < NCH; ch++) {
        if (ch + 1 < NCH) {
            int k0 = (ch + 1) * 32;
            ld2(pah, g_Tch, 256, k0, tid);
            ld2(pal, g_Tcl, 256, k0, tid);
#pragma unroll
            for (int t = 0; t < 4; t++) {
                int f = tid + t * 256, row = f >> 3, c4 = f & 7;
                px[t] = *(const float4*)&xb[row * 256 + k0 + c4 * 4];
            }
        }
        wchunk_hl(c, sb + (ch & 1) * 40960, lane, wy, wx);
        if (ch + 1 < NCH) {
            int o = ((ch + 1) & 1) * 40960;
            st2(smem, o, pah, tid);
            st2(smem, o + 10240, pal, tid);
#pragma unroll
            for (int t = 0; t < 4; t++) {
                int f = tid + t * 256, row = f >> 3, c4 = f & 7;
                int off = (row * 40 + c4 * 4) * 2;
                float4 v = px[t];
                *(uint2*)(smem + o + 20480 + off) = make_uint2(pack_h(v.x, v.y), pack_h(v.z, v.w));
                *(uint2*)(smem + o + 30720 + off) = make_uint2(pack_l(v.x, v.y), pack_l(v.z, v.w));
            }
            __syncthreads();
        }
    }
    int g = lane >> 2, cp = (lane & 3) * 2;
#pragma unroll
    for (int mi = 0; mi < 2; mi++)
#pragma unroll
        for (int ni = 0; ni < 8; ni++) {
            int col = mh * 128 + wx * 64 + ni * 8 + cp;
            int r0 = wy * 32 + mi * 16 + g;
            int b0 = (img * 128 + r0) * 256 + col;
            int b1 = b0 + 8 * 256;
            float* d = c[mi][ni];
            *(u32*)&g_Uth[b0] = pack_h(d[0], d[1]);
            *(u32*)&g_Utl[b0] = pack_l(d[0], d[1]);
            *(u32*)&g_Uth[b1] = pack_h(d[2], d[3]);
            *(u32*)&g_Utl[b1] = pack_l(d[2], d[3]);
        }
}

// ---------------- K2 ----------------
__global__ __launch_bounds__(256) void k2_fwd() {
    extern __shared__ char smem[];
    u32 sb = smem_u32(smem);
    int tid = threadIdx.x, lane = tid & 31, w = tid >> 5, wy = w >> 1, wx = w & 1;
    int img = blockIdx.x;
    float c[2][8][4];
#pragma unroll
    for (int i = 0; i < 2; i++)
#pragma unroll
        for (int j = 0; j < 8; j++)
#pragma unroll
            for (int r = 0; r < 4; r++) c[i][j][r] = 0.f;
    gmain_hl<8>(g_Tch, g_Tcl, g_Uth + img * 32768, g_Utl + img * 32768,
                256, 256, c, smem, sb, tid, lane, wy, wx);
    __syncthreads();   // buffers done; reuse smem for F staging
    float* F = (float*)smem;  // [128][132]
    int g = lane >> 2, cp = (lane & 3) * 2;
#pragma unroll
    for (int mi = 0; mi < 2; mi++)
#pragma unroll
        for (int ni = 0; ni < 8; ni++) {
            int col = wx * 64 + ni * 8 + cp;
            int r0 = wy * 32 + mi * 16 + g;
            float* d = c[mi][ni];
            F[r0 * 132 + col] = d[0];
            F[r0 * 132 + col + 1] = d[1];
            F[(r0 + 8) * 132 + col] = d[2];
            F[(r0 + 8) * 132 + col + 1] = d[3];
        }
    __syncthreads();
    const int b = img >> 6, ic = img & 63;
#pragma unroll
    for (int t = 0; t < 16; t++) {
        int p = tid + t * 256;
        int s1 = p >> 6, s2 = p & 63;
        float r00 = F[s1 * 132 + s2];
        float r01 = F[s1 * 132 + 64 + s2];
        float r10 = F[(64 + s1) * 132 + s2];
        float r11 = F[(64 + s1) * 132 + 64 + s2];
        int a = p * 1024 + ic * 16 + b;
        g_CS[a] = r00 - r11;
        g_CS[4194304 + a] = r10 + r01;
    }
}

// ---------------- K3: channel mixing (fp32) ----------------
__device__ __forceinline__ ull pk2(float lo, float hi) {
    ull r; asm("mov.b64 %0, {%1, %2};" : "=l"(r) : "f"(lo), "f"(hi)); return r;
}
__device__ __forceinline__ float2 up2(ull v) {
    float2 f; asm("mov.b64 {%0, %1}, %2;" : "=f"(f.x), "=f"(f.y) : "l"(v)); return f;
}
__device__ __forceinline__ void fm2(ull& d, ull a, ull b) {
    asm("fma.rn.f32x2 %0, %1, %2, %0;" : "+l"(d) : "l"(a), "l"(b));
}
__global__ __launch_bounds__(256) void k_mix() {
    __shared__ float sC[1024], sS[1024];
    __shared__ float sW[4096], sWr[4096];
    const int mode = blockIdx.x;
    const int s1 = mode >> 6, s2 = mode & 63;
    const int f1 = (64 - s1) & 63, f2 = (64 - s2) & 63;
    const int tid = threadIdx.x;
    for (int t = tid; t < 1024; t += 256) {
        sC[t] = g_CS[mode * 1024 + t];
        sS[t] = g_CS[4194304 + mode * 1024 + t];
    }
    for (int t = tid; t < 4096; t += 256) {
        sW[t] = g_Wt[mode * 4096 + t];
        sWr[t] = g_Wt[(f1 * 64 + f2) * 4096 + t];
    }
    __syncthreads();
    const int o = tid & 63, bq = tid >> 6;
    ull acc01 = 0ull, acc23 = 0ull;
#pragma unroll 8
    for (int i = 0; i < 64; i++) {
        float wv = sW[i * 64 + o];
        float wr = sWr[i * 64 + o];
        ull ww = pk2(wv, wv), wwr = pk2(wr, wr);
        fm2(acc01, *(const ull*)&sC[i * 16 + bq * 4], ww);
        fm2(acc01, *(const ull*)&sS[i * 16 + bq * 4], wwr);
        fm2(acc23, *(const ull*)&sC[i * 16 + bq * 4 + 2], ww);
        fm2(acc23, *(const ull*)&sS[i * 16 + bq * 4 + 2], wwr);
    }
    float2 v01 = up2(acc01), v23 = up2(acc23);
    float vals[4] = {v01.x, v01.y, v23.x, v23.y};
#pragma unroll
    for (int r = 0; r < 4; r++) {
        int img2 = (bq * 4 + r) * 64 + o;
        bf16 h, l;
        bsplit(vals[r], h, l);
        g_Tth[img2 * 4096 + s2 * 64 + s1] = h;
        g_Ttl[img2 * 4096 + s2 * 64 + s1] = l;
    }
}

// ---------------- K4: M=256 (c,m), N=64, K=64, 3 segs (unchanged) ----------------
__global__ __launch_bounds__(256) void k4_inv() {
    extern __shared__ char smem[];
    u32 sb = smem_u32(smem);
    int tid = threadIdx.x, lane = tid & 31, w = tid >> 5, wy = w >> 1, wx = w & 1;
    int img = blockIdx.x >> 1, m0 = (blockIdx.x & 1) * 128;
    const bf16* As[3] = {g_A5h, g_A5h, g_A5l};
    const bf16* Bs[3] = {g_Tth + img * 4096, g_Ttl + img * 4096, g_Tth + img * 4096};
    const int ASZ = 20480, BUF = ASZ + 5120;
    float c[4][4][4];
#pragma unroll
    for (int i = 0; i < 4; i++)
#pragma unroll
        for (int j = 0; j < 4; j++)
#pragma unroll
            for (int r = 0; r < 4; r++) c[i][j][r] = 0.f;
    uint4 pa[4], pb;
    {
#pragma unroll
        for (int t = 0; t < 4; t++) {
            int f = tid + t * 256, row = f >> 2, cc = f & 3;
            int gr = (row < 128) ? (m0 + row) : (256 + m0 + row - 128);
            pa[t] = *(const uint4*)&As[0][gr * 64 + cc * 8];
        }
        int row = tid >> 2, cc = tid & 3;
        pb = *(const uint4*)&Bs[0][row * 64 + cc * 8];
#pragma unroll
        for (int t = 0; t < 4; t++) {
            int f = tid + t * 256, row2 = f >> 2, c2 = f & 3;
            *(uint4*)(smem + (row2 * 40 + c2 * 8) * 2) = pa[t];
        }
        *(uint4*)(smem + ASZ + (row * 40 + cc * 8) * 2) = pb;
    }
    __syncthreads();
    const int NCH = 6;
    for (int ch = 0; ch < NCH; ch++) {
        if (ch + 1 < NCH) {
            int seg = (ch + 1) / 2, k0 = ((ch + 1) % 2) * 32;
#pragma unroll
            for (int t = 0; t < 4; t++) {
                int f = tid + t * 256, row = f >> 2, cc = f & 3;
                int gr = (row < 128) ? (m0 + row) : (256 + m0 + row - 128);
                pa[t] = *(const uint4*)&As[seg][gr * 64 + k0 + cc * 8];
            }
            int row = tid >> 2, cc = tid & 3;
            pb = *(const uint4*)&Bs[seg][row * 64 + k0 + cc * 8];
        }
        {
            u32 sA = sb + (ch & 1) * BUF, sB = sA + ASZ;
            int rowA = wy * 64 + (lane & 15);
            int colA = (lane >> 4) * 8;
            int rowB = wx * 32 + (lane & 7) + ((lane >> 4) << 3);
            int colB = ((lane >> 3) & 1) * 8;
#pragma unroll
            for (int kk = 0; kk < 32; kk += 16) {
                u32 a[4][4], b[2][4];
#pragma unroll
                for (int mi = 0; mi < 4; mi++)
                    ldsm4(a[mi], sA + ((rowA + mi * 16) * 40 + kk + colA) * 2);
#pragma unroll
                for (int np = 0; np < 2; np++)
                    ldsm4(b[np], sB + ((rowB + np * 16) * 40 + kk + colB) * 2);
#pragma unroll
                for (int mi = 0; mi < 4; mi++)
#pragma unroll
                    for (int ni = 0; ni < 4; ni++)
                        mmabf(c[mi][ni], a[mi], &b[ni >> 1][(ni & 1) * 2]);
            }
        }
        if (ch + 1 < NCH) {
            int o = ((ch + 1) & 1) * BUF;
#pragma unroll
            for (int t = 0; t < 4; t++) {
                int f = tid + t * 256, row = f >> 2, cc = f & 3;
                *(uint4*)(smem + o + (row * 40 + cc * 8) * 2) = pa[t];
            }
            int row = tid >> 2, cc = tid & 3;
            *(uint4*)(smem + o + ASZ + (row * 40 + cc * 8) * 2) = pb;
            __syncthreads();
        }
    }
    int g = lane >> 2, cp = (lane & 3) * 2;
#pragma unroll
    for (int mi = 0; mi < 4; mi++)
#pragma unroll
        for (int ni = 0; ni < 4; ni++) {
            int s2 = wx * 32 + ni * 8 + cp;
            float* d = c[mi][ni];
#pragma unroll
            for (int half = 0; half < 2; half++) {
                int rL = wy * 64 + mi * 16 + g + half * 8;
                int cc = rL >> 7, m = m0 + (rL & 127);
                int idx = (img * 256 + m) * 128 + cc * 64 + s2;
                *(u32*)&g_Wh[idx] = pack_h(d[half * 2], d[half * 2 + 1]);
                *(u32*)&g_Wl[idx] = pack_l(d[half * 2], d[half * 2 + 1]);
            }
        }
}

// ---------------- K5 ----------------
__global__ __launch_bounds__(256) void k5_inv(const float* __restrict__ bias,
                                              float* __restrict__ out) {
    extern __shared__ char smem[];
    u32 sb = smem_u32(smem);
    int tid = threadIdx.x, lane = tid & 31, w = tid >> 5, wy = w >> 1, wx = w & 1;
    int n0 = blockIdx.x * 128, m0 = blockIdx.y * 128, img = blockIdx.z;
    float c[2][8][4];
#pragma unroll
    for (int i = 0; i < 2; i++)
#pragma unroll
        for (int j = 0; j < 8; j++)
#pragma unroll
            for (int r = 0; r < 4; r++) c[i][j][r] = 0.f;
    gmain_hl<4>(g_Wh + (img * 256 + m0) * 128, g_Wl + (img * 256 + m0) * 128,
                g_T5h + n0 * 128, g_T5l + n0 * 128,
                128, 128, c, smem, sb, tid, lane, wy, wx);
    const float bv = bias[img & 63];
    const float sc = 1.0f / 65536.0f;
    int g = lane >> 2, cp = (lane & 3) * 2;
#pragma unroll
    for (int mi = 0; mi < 2; mi++)
#pragma unroll
        for (int ni = 0; ni < 8; ni++) {
            int col = n0 + wx * 64 + ni * 8 + cp;
            float* d = c[mi][ni];
#pragma unroll
            for (int half = 0; half < 2; half++) {
                int m = m0 + wy * 32 + mi * 16 + g + half * 8;
                float2 v;
                v.x = fmaxf(fmaf(d[half * 2], sc, bv), 0.f);
                v.y = fmaxf(fmaf(d[half * 2 + 1], sc, bv), 0.f);
                *(float2*)&out[(img * 256 + m) * 256 + col] = v;
            }
        }
}

extern "C" void kernel_launch(void* const* d_in, const int* in_sizes, int n_in,
                              void* d_out, int out_size) {
    const float* x = (const float*)d_in[0];
    const float* wgt = (const float*)d_in[1];
    const float* bias = (const float*)d_in[2];
    float* out = (float*)d_out;

    cudaFuncSetAttribute(k1_fwd, cudaFuncAttributeMaxDynamicSharedMemorySize, 81920);
    cudaFuncSetAttribute(k2_fwd, cudaFuncAttributeMaxDynamicSharedMemorySize, 81920);
    cudaFuncSetAttribute(k4_inv, cudaFuncAttributeMaxDynamicSharedMemorySize, 51200);
    cudaFuncSetAttribute(k5_inv, cudaFuncAttributeMaxDynamicSharedMemorySize, 81920);

    k_tables<<<256, 128>>>();
    k_wt<<<dim3(128, 128), dim3(32, 8)>>>(wgt);
    k1_fwd<<<2048, 256, 81920>>>(x);
    k2_fwd<<<1024, 256, 81920>>>();
    k_mix<<<4096, 256>>>();
    k4_inv<<<2048, 256, 51200>>>();
    k5_inv<<<dim3(2, 2, 1024), 256, 81920>>>(bias, out);
}

// round 8
// speedup vs baseline: 1.5904x; 1.1464x over previous
#include <cuda_runtime.h>
#include <cuda_bf16.h>
#include <cstdint>

// HartleySpectralConv2d B=16,CI=CO=64,H=W=256, modes 64x64.
// Split-bf16 GEMMs on mma.sync.m16n8k16, fp32 accum, cp.async pipelines, 2 CTA/SM.

using bf16 = __nv_bfloat16;
using u32 = uint32_t; using ull = unsigned long long;

__device__ bf16 g_Tch[128 * 256], g_Tcl[128 * 256];       // [j][n] K-major
__device__ bf16 g_A5h[2 * 256 * 64], g_A5l[2 * 256 * 64]; // [(c*256+m)][s1]
__device__ bf16 g_T5h[256 * 128], g_T5l[256 * 128];       // [n][c*64+s2]
__device__ bf16 g_Uth[1024 * 128 * 256], g_Utl[1024 * 128 * 256]; // [img][j][m]
__device__ float g_Wt[4096 * 4096];                       // [mode][i*64+o]
__device__ float g_CS[2 * 4096 * 1024];                   // [comp][mode][ci*16+b]
__device__ bf16 g_Tth[1024 * 4096], g_Ttl[1024 * 4096];   // [img][s2*64+s1]
__device__ bf16 g_Wh[1024 * 256 * 128], g_Wl[1024 * 256 * 128]; // [img][m][k]

// ---------------- helpers ----------------
__device__ __forceinline__ u32 smem_u32(const void* p) {
    u32 a;
    asm("{ .reg .u64 t; cvta.to.shared.u64 t, %1; cvt.u32.u64 %0, t; }" : "=r"(a) : "l"(p));
    return a;
}
__device__ __forceinline__ void ldsm4(u32* r, u32 a) {
    asm volatile("ldmatrix.sync.aligned.m8n8.x4.shared.b16 {%0,%1,%2,%3}, [%4];"
                 : "=r"(r[0]), "=r"(r[1]), "=r"(r[2]), "=r"(r[3]) : "r"(a));
}
__device__ __forceinline__ void mmabf(float* d, const u32* a, const u32* b) {
    asm volatile("mma.sync.aligned.m16n8k16.row.col.f32.bf16.bf16.f32 "
                 "{%0,%1,%2,%3}, {%4,%5,%6,%7}, {%8,%9}, {%0,%1,%2,%3};"
                 : "+f"(d[0]), "+f"(d[1]), "+f"(d[2]), "+f"(d[3])
                 : "r"(a[0]), "r"(a[1]), "r"(a[2]), "r"(a[3]), "r"(b[0]), "r"(b[1]));
}
__device__ __forceinline__ void cpa(u32 s, const void* g) {
    asm volatile("cp.async.cg.shared.global [%0], [%1], 16;" :: "r"(s), "l"(g));
}
#define CPC()  asm volatile("cp.async.commit_group;" ::: "memory")
#define CPW1() asm volatile("cp.async.wait_group 1;" ::: "memory")
#define CPW0() asm volatile("cp.async.wait_group 0;" ::: "memory")

__device__ __forceinline__ u32 pack_bf(bf16 a, bf16 b) {
    return (u32)__bfloat16_as_ushort(a) | ((u32)__bfloat16_as_ushort(b) << 16);
}
__device__ __forceinline__ void bsplit(float v, bf16& h, bf16& l) {
    h = __float2bfloat16(v);
    l = __float2bfloat16(v - __bfloat162float(h));
}
__device__ __forceinline__ u32 pack_h(float a, float b) {
    bf16 h0, l0, h1, l1; bsplit(a, h0, l0); bsplit(b, h1, l1); return pack_bf(h0, h1);
}
__device__ __forceinline__ u32 pack_l(float a, float b) {
    bf16 h0, l0, h1, l1; bsplit(a, h0, l0); bsplit(b, h1, l1); return pack_bf(l0, l1);
}

// cp.async a 128x32 bf16 tile (row stride 40 elems) from [ld]-strided src
__device__ __forceinline__ void cp_tile(u32 sbase, const bf16* __restrict__ src,
                                        int ld, int k0, int tid) {
#pragma unroll
    for (int t = 0; t < 2; t++) {
        int f = tid + t * 256, row = f >> 2, c = f & 3;
        cpa(sbase + (row * 40 + c * 8) * 2, &src[(long long)row * ld + k0 + c * 8]);
    }
}
// Buffer: Ah@0, Al@10240, Bh@20480, Bl@30720 (40960B each, x2)
__device__ __forceinline__ void issue4(u32 sb, int bufo,
                                       const bf16* Ah, const bf16* Al,
                                       const bf16* Bh, const bf16* Bl,
                                       int lda, int ldb, int k0, int tid) {
    cp_tile(sb + bufo, Ah, lda, k0, tid);
    cp_tile(sb + bufo + 10240, Al, lda, k0, tid);
    cp_tile(sb + bufo + 20480, Bh, ldb, k0, tid);
    cp_tile(sb + bufo + 30720, Bl, ldb, k0, tid);
    CPC();
}
// warp tile 32(m) x 64(n), k-chunk 32; acc += AhBh + AhBl + AlBh
__device__ __forceinline__ void wchunk_hl(float c[2][8][4], u32 base, int lane, int wy, int wx) {
    int rowA = wy * 32 + (lane & 15);
    int colA = (lane >> 4) * 8;
    int rowB = wx * 64 + (lane & 7) + ((lane >> 4) << 3);
    int colB = ((lane >> 3) & 1) * 8;
#pragma unroll
    for (int kk = 0; kk < 32; kk += 16) {
        u32 ah[2][4], al[2][4], bh[4][4], bl[4][4];
#pragma unroll
        for (int mi = 0; mi < 2; mi++) {
            u32 ao = ((rowA + mi * 16) * 40 + kk + colA) * 2;
            ldsm4(ah[mi], base + ao);
            ldsm4(al[mi], base + 10240 + ao);
        }
#pragma unroll
        for (int np = 0; np < 4; np++) {
            u32 bo = ((rowB + np * 16) * 40 + kk + colB) * 2;
            ldsm4(bh[np], base + 20480 + bo);
            ldsm4(bl[np], base + 30720 + bo);
        }
#pragma unroll
        for (int mi = 0; mi < 2; mi++)
#pragma unroll
            for (int ni = 0; ni < 8; ni++)
                mmabf(c[mi][ni], ah[mi], &bh[ni >> 1][(ni & 1) * 2]);
#pragma unroll
        for (int mi = 0; mi < 2; mi++)
#pragma unroll
            for (int ni = 0; ni < 8; ni++)
                mmabf(c[mi][ni], ah[mi], &bl[ni >> 1][(ni & 1) * 2]);
#pragma unroll
        for (int mi = 0; mi < 2; mi++)
#pragma unroll
            for (int ni = 0; ni < 8; ni++)
                mmabf(c[mi][ni], al[mi], &bh[ni >> 1][(ni & 1) * 2]);
    }
}
// full-async mainloop (A,B h/l pairs in global)
template <int NCH>
__device__ __forceinline__ void gmain_ca(const bf16* Ah, const bf16* Al,
                                         const bf16* Bh, const bf16* Bl,
                                         int lda, int ldb, float c[2][8][4],
                                         u32 sb, int tid, int lane, int wy, int wx) {
    issue4(sb, 0, Ah, Al, Bh, Bl, lda, ldb, 0, tid);
    issue4(sb, 40960, Ah, Al, Bh, Bl, lda, ldb, 32, tid);
    for (int ch = 0; ch < NCH; ch++) {
        if (ch + 1 < NCH) { CPW1(); } else { CPW0(); }
        __syncthreads();
        wchunk_hl(c, sb + (ch & 1) * 40960, lane, wy, wx);
        if (ch + 2 < NCH) {
            __syncthreads();
            issue4(sb, (ch & 1) * 40960, Ah, Al, Bh, Bl, lda, ldb, (ch + 2) * 32, tid);
        }
    }
}

// ---------------- K0: split trig tables ----------------
__global__ void k_tables() {
    int a = blockIdx.x, b = threadIdx.x;
    int s = b & 63, k = s - 32;
    int q = ((k * a) % 256 + 256) % 256;
    float sv, cv;
    sincospif((float)q * (1.0f / 128.0f), &sv, &cv);
    float tc = (b < 64) ? cv : sv;
    bf16 h, l;
    bsplit(tc, h, l);
    g_Tch[b * 256 + a] = h; g_Tcl[b * 256 + a] = l;
    g_T5h[a * 128 + b] = h; g_T5l[a * 128 + b] = l;
    int c = b >> 6;
    float a5 = c ? (cv - sv) : (cv + sv);
    bsplit(a5, h, l);
    g_A5h[(c * 256 + a) * 64 + s] = h;
    g_A5l[(c * 256 + a) * 64 + s] = l;
}

// ---------------- Kw: weight transpose ----------------
__global__ void k_wt(const float* __restrict__ w) {
    __shared__ float tile[32][33];
    int x0 = blockIdx.x * 32, y0 = blockIdx.y * 32;
    int tx = threadIdx.x, ty = threadIdx.y;
#pragma unroll
    for (int r = 0; r < 32; r += 8)
        tile[ty + r][tx] = w[(y0 + ty + r) * 4096 + x0 + tx];
    __syncthreads();
#pragma unroll
    for (int r = 0; r < 32; r += 8)
        g_Wt[(x0 + ty + r) * 4096 + y0 + tx] = tile[tx][ty + r];
}

// ---------------- K1: tables via cp.async, x split in-register ----------------
__global__ __launch_bounds__(256, 2) void k1_fwd(const float* __restrict__ x) {
    extern __shared__ char smem[];
    u32 sb = smem_u32(smem);
    int tid = threadIdx.x, lane = tid & 31, w = tid >> 5, wy = w >> 1, wx = w & 1;
    int mt = blockIdx.x, img = mt >> 1, mh = mt & 1;
    const float* xb = x + (long long)mt * 128 * 256;
    float c[2][8][4];
#pragma unroll
    for (int i = 0; i < 2; i++)
#pragma unroll
        for (int j = 0; j < 8; j++)
#pragma unroll
            for (int r = 0; r < 4; r++) c[i][j][r] = 0.f;

    // prologue: tables chunk0 -> buf0, chunk1 -> buf1 (cp.async); x chunk0 -> buf0 (regs)
    cp_tile(sb, g_Tch, 256, 0, tid);
    cp_tile(sb + 10240, g_Tcl, 256, 0, tid);
    CPC();
    cp_tile(sb + 40960, g_Tch, 256, 32, tid);
    cp_tile(sb + 40960 + 10240, g_Tcl, 256, 32, tid);
    CPC();
    float4 px[4];
#pragma unroll
    for (int t = 0; t < 4; t++) {
        int f = tid + t * 256, row = f >> 3, c4 = f & 7;
        px[t] = *(const float4*)&xb[row * 256 + c4 * 4];
    }
#pragma unroll
    for (int t = 0; t < 4; t++) {
        int f = tid + t * 256, row = f >> 3, c4 = f & 7;
        int off = (row * 40 + c4 * 4) * 2;
        float4 v = px[t];
        *(uint2*)(smem + 20480 + off) = make_uint2(pack_h(v.x, v.y), pack_h(v.z, v.w));
        *(uint2*)(smem + 30720 + off) = make_uint2(pack_l(v.x, v.y), pack_l(v.z, v.w));
    }
    CPW1();
    __syncthreads();
    const int NCH = 8;
    for (int ch = 0; ch < NCH; ch++) {
        if (ch + 1 < NCH) {
            int k0 = (ch + 1) * 32;
#pragma unroll
            for (int t = 0; t < 4; t++) {
                int f = tid + t * 256, row = f >> 3, c4 = f & 7;
                px[t] = *(const float4*)&xb[row * 256 + k0 + c4 * 4];
            }
        }
        wchunk_hl(c, sb + (ch & 1) * 40960, lane, wy, wx);
        if (ch + 1 < NCH) {
            CPW0();            // tables for ch+1 have landed
            __syncthreads();   // all warps done with buf[ch&1]
            int o = ((ch + 1) & 1) * 40960;
#pragma unroll
            for (int t = 0; t < 4; t++) {
                int f = tid + t * 256, row = f >> 3, c4 = f & 7;
                int off = (row * 40 + c4 * 4) * 2;
                float4 v = px[t];
                *(uint2*)(smem + o + 20480 + off) = make_uint2(pack_h(v.x, v.y), pack_h(v.z, v.w));
                *(uint2*)(smem + o + 30720 + off) = make_uint2(pack_l(v.x, v.y), pack_l(v.z, v.w));
            }
            if (ch + 2 < NCH) {
                int bo = (ch & 1) * 40960;
                cp_tile(sb + bo, g_Tch, 256, (ch + 2) * 32, tid);
                cp_tile(sb + bo + 10240, g_Tcl, 256, (ch + 2) * 32, tid);
                CPC();
            }
            __syncthreads();
        }
    }
    int g = lane >> 2, cp = (lane & 3) * 2;
#pragma unroll
    for (int mi = 0; mi < 2; mi++)
#pragma unroll
        for (int ni = 0; ni < 8; ni++) {
            int col = mh * 128 + wx * 64 + ni * 8 + cp;
            int r0 = wy * 32 + mi * 16 + g;
            int b0 = (img * 128 + r0) * 256 + col;
            int b1 = b0 + 8 * 256;
            float* d = c[mi][ni];
            *(u32*)&g_Uth[b0] = pack_h(d[0], d[1]);
            *(u32*)&g_Utl[b0] = pack_l(d[0], d[1]);
            *(u32*)&g_Uth[b1] = pack_h(d[2], d[3]);
            *(u32*)&g_Utl[b1] = pack_l(d[2], d[3]);
        }
}

// ---------------- K2 ----------------
__global__ __launch_bounds__(256, 2) void k2_fwd() {
    extern __shared__ char smem[];
    u32 sb = smem_u32(smem);
    int tid = threadIdx.x, lane = tid & 31, w = tid >> 5, wy = w >> 1, wx = w & 1;
    int img = blockIdx.x;
    float c[2][8][4];
#pragma unroll
    for (int i = 0; i < 2; i++)
#pragma unroll
        for (int j = 0; j < 8; j++)
#pragma unroll
            for (int r = 0; r < 4; r++) c[i][j][r] = 0.f;
    gmain_ca<8>(g_Tch, g_Tcl, g_Uth + img * 32768, g_Utl + img * 32768,
                256, 256, c, sb, tid, lane, wy, wx);
    __syncthreads();
    float* F = (float*)smem;  // [128][132]
    int g = lane >> 2, cp = (lane & 3) * 2;
#pragma unroll
    for (int mi = 0; mi < 2; mi++)
#pragma unroll
        for (int ni = 0; ni < 8; ni++) {
            int col = wx * 64 + ni * 8 + cp;
            int r0 = wy * 32 + mi * 16 + g;
            float* d = c[mi][ni];
            F[r0 * 132 + col] = d[0];
            F[r0 * 132 + col + 1] = d[1];
            F[(r0 + 8) * 132 + col] = d[2];
            F[(r0 + 8) * 132 + col + 1] = d[3];
        }
    __syncthreads();
    const int b = img >> 6, ic = img & 63;
#pragma unroll
    for (int t = 0; t < 16; t++) {
        int p = tid + t * 256;
        int s1 = p >> 6, s2 = p & 63;
        float r00 = F[s1 * 132 + s2];
        float r01 = F[s1 * 132 + 64 + s2];
        float r10 = F[(64 + s1) * 132 + s2];
        float r11 = F[(64 + s1) * 132 + 64 + s2];
        int a = p * 1024 + ic * 16 + b;
        g_CS[a] = r00 - r11;
        g_CS[4194304 + a] = r10 + r01;
    }
}

// ---------------- K3: channel mixing (fp32) ----------------
__device__ __forceinline__ ull pk2(float lo, float hi) {
    ull r; asm("mov.b64 %0, {%1, %2};" : "=l"(r) : "f"(lo), "f"(hi)); return r;
}
__device__ __forceinline__ float2 up2(ull v) {
    float2 f; asm("mov.b64 {%0, %1}, %2;" : "=f"(f.x), "=f"(f.y) : "l"(v)); return f;
}
__device__ __forceinline__ void fm2(ull& d, ull a, ull b) {
    asm("fma.rn.f32x2 %0, %1, %2, %0;" : "+l"(d) : "l"(a), "l"(b));
}
__global__ __launch_bounds__(256) void k_mix() {
    __shared__ float sC[1024], sS[1024];
    __shared__ float sW[4096], sWr[4096];
    const int mode = blockIdx.x;
    const int s1 = mode >> 6, s2 = mode & 63;
    const int f1 = (64 - s1) & 63, f2 = (64 - s2) & 63;
    const int tid = threadIdx.x;
    for (int t = tid; t < 1024; t += 256) {
        sC[t] = g_CS[mode * 1024 + t];
        sS[t] = g_CS[4194304 + mode * 1024 + t];
    }
    for (int t = tid; t < 4096; t += 256) {
        sW[t] = g_Wt[mode * 4096 + t];
        sWr[t] = g_Wt[(f1 * 64 + f2) * 4096 + t];
    }
    __syncthreads();
    const int o = tid & 63, bq = tid >> 6;
    ull acc01 = 0ull, acc23 = 0ull;
#pragma unroll 8
    for (int i = 0; i < 64; i++) {
        float wv = sW[i * 64 + o];
        float wr = sWr[i * 64 + o];
        ull ww = pk2(wv, wv), wwr = pk2(wr, wr);
        fm2(acc01, *(const ull*)&sC[i * 16 + bq * 4], ww);
        fm2(acc01, *(const ull*)&sS[i * 16 + bq * 4], wwr);
        fm2(acc23, *(const ull*)&sC[i * 16 + bq * 4 + 2], ww);
        fm2(acc23, *(const ull*)&sS[i * 16 + bq * 4 + 2], wwr);
    }
    float2 v01 = up2(acc01), v23 = up2(acc23);
    float vals[4] = {v01.x, v01.y, v23.x, v23.y};
#pragma unroll
    for (int r = 0; r < 4; r++) {
        int img2 = (bq * 4 + r) * 64 + o;
        bf16 h, l;
        bsplit(vals[r], h, l);
        g_Tth[img2 * 4096 + s2 * 64 + s1] = h;
        g_Ttl[img2 * 4096 + s2 * 64 + s1] = l;
    }
}

// ---------------- K4: M=256(c,m), N=64, K=64, 3 segs, cp.async ----------------
__device__ __forceinline__ void k4_issue(u32 sb, int bufo, const bf16* __restrict__ A,
                                         const bf16* __restrict__ B, int m0, int k0, int tid) {
#pragma unroll
    for (int t = 0; t < 4; t++) {
        int f = tid + t * 256, row = f >> 2, cc = f & 3;
        int gr = (row < 128) ? (m0 + row) : (256 + m0 + row - 128);
        cpa(sb + bufo + (row * 40 + cc * 8) * 2, &A[gr * 64 + k0 + cc * 8]);
    }
    {
        int row = tid >> 2, cc = tid & 3;
        cpa(sb + bufo + 20480 + (row * 40 + cc * 8) * 2, &B[row * 64 + k0 + cc * 8]);
    }
    CPC();
}
__global__ __launch_bounds__(256, 2) void k4_inv() {
    extern __shared__ char smem[];
    u32 sb = smem_u32(smem);
    int tid = threadIdx.x, lane = tid & 31, w = tid >> 5, wy = w >> 1, wx = w & 1;
    int img = blockIdx.x >> 1, m0 = (blockIdx.x & 1) * 128;
    const bf16* As[3] = {g_A5h, g_A5h, g_A5l};
    const bf16* Bs[3] = {g_Tth + img * 4096, g_Ttl + img * 4096, g_Tth + img * 4096};
    const int BUF = 25600;
    float c[4][4][4];
#pragma unroll
    for (int i = 0; i < 4; i++)
#pragma unroll
        for (int j = 0; j < 4; j++)
#pragma unroll
            for (int r = 0; r < 4; r++) c[i][j][r] = 0.f;
    k4_issue(sb, 0, As[0], Bs[0], m0, 0, tid);
    k4_issue(sb, BUF, As[0], Bs[0], m0, 32, tid);
    const int NCH = 6;
    for (int ch = 0; ch < NCH; ch++) {
        if (ch + 1 < NCH) { CPW1(); } else { CPW0(); }
        __syncthreads();
        {
            u32 sA = sb + (ch & 1) * BUF, sB = sA + 20480;
            int rowA = wy * 64 + (lane & 15);
            int colA = (lane >> 4) * 8;
            int rowB = wx * 32 + (lane & 7) + ((lane >> 4) << 3);
            int colB = ((lane >> 3) & 1) * 8;
#pragma unroll
            for (int kk = 0; kk < 32; kk += 16) {
                u32 a[4][4], b[2][4];
#pragma unroll
                for (int mi = 0; mi < 4; mi++)
                    ldsm4(a[mi], sA + ((rowA + mi * 16) * 40 + kk + colA) * 2);
#pragma unroll
                for (int np = 0; np < 2; np++)
                    ldsm4(b[np], sB + ((rowB + np * 16) * 40 + kk + colB) * 2);
#pragma unroll
                for (int mi = 0; mi < 4; mi++)
#pragma unroll
                    for (int ni = 0; ni < 4; ni++)
                        mmabf(c[mi][ni], a[mi], &b[ni >> 1][(ni & 1) * 2]);
            }
        }
        if (ch + 2 < NCH) {
            __syncthreads();
            int seg = (ch + 2) / 2, k0 = ((ch + 2) % 2) * 32;
            k4_issue(sb, (ch & 1) * BUF, As[seg], Bs[seg], m0, k0, tid);
        }
    }
    int g = lane >> 2, cp = (lane & 3) * 2;
#pragma unroll
    for (int mi = 0; mi < 4; mi++)
#pragma unroll
        for (int ni = 0; ni < 4; ni++) {
            int s2 = wx * 32 + ni * 8 + cp;
            float* d = c[mi][ni];
#pragma unroll
            for (int half = 0; half < 2; half++) {
                int rL = wy * 64 + mi * 16 + g + half * 8;
                int cc = rL >> 7, m = m0 + (rL & 127);
                int idx = (img * 256 + m) * 128 + cc * 64 + s2;
                *(u32*)&g_Wh[idx] = pack_h(d[half * 2], d[half * 2 + 1]);
                *(u32*)&g_Wl[idx] = pack_l(d[half * 2], d[half * 2 + 1]);
            }
        }
}

// ---------------- K5 ----------------
__global__ __launch_bounds__(256, 2) void k5_inv(const float* __restrict__ bias,
                                                 float* __restrict__ out) {
    extern __shared__ char smem[];
    u32 sb = smem_u32(smem);
    int tid = threadIdx.x, lane = tid & 31, w = tid >> 5, wy = w >> 1, wx = w & 1;
    int n0 = blockIdx.x * 128, m0 = blockIdx.y * 128, img = blockIdx.z;
    float c[2][8][4];
#pragma unroll
    for (int i = 0; i < 2; i++)
#pragma unroll
        for (int j = 0; j < 8; j++)
#pragma unroll
            for (int r = 0; r < 4; r++) c[i][j][r] = 0.f;
    gmain_ca<4>(g_Wh + (img * 256 + m0) * 128, g_Wl + (img * 256 + m0) * 128,
                g_T5h + n0 * 128, g_T5l + n0 * 128,
                128, 128, c, sb, tid, lane, wy, wx);
    const float bv = bias[img & 63];
    const float sc = 1.0f / 65536.0f;
    int g = lane >> 2, cp = (lane & 3) * 2;
#pragma unroll
    for (int mi = 0; mi < 2; mi++)
#pragma unroll
        for (int ni = 0; ni < 8; ni++) {
            int col = n0 + wx * 64 + ni * 8 + cp;
            float* d = c[mi][ni];
#pragma unroll
            for (int half = 0; half < 2; half++) {
                int m = m0 + wy * 32 + mi * 16 + g + half * 8;
                float2 v;
                v.x = fmaxf(fmaf(d[half * 2], sc, bv), 0.f);
                v.y = fmaxf(fmaf(d[half * 2 + 1], sc, bv), 0.f);
                *(float2*)&out[(img * 256 + m) * 256 + col] = v;
            }
        }
}

extern "C" void kernel_launch(void* const* d_in, const int* in_sizes, int n_in,
                              void* d_out, int out_size) {
    const float* x = (const float*)d_in[0];
    const float* wgt = (const float*)d_in[1];
    const float* bias = (const float*)d_in[2];
    float* out = (float*)d_out;

    cudaFuncSetAttribute(k1_fwd, cudaFuncAttributeMaxDynamicSharedMemorySize, 81920);
    cudaFuncSetAttribute(k2_fwd, cudaFuncAttributeMaxDynamicSharedMemorySize, 81920);
    cudaFuncSetAttribute(k4_inv, cudaFuncAttributeMaxDynamicSharedMemorySize, 51200);
    cudaFuncSetAttribute(k5_inv, cudaFuncAttributeMaxDynamicSharedMemorySize, 81920);

    k_tables<<<256, 128>>>();
    k_wt<<<dim3(128, 128), dim3(32, 8)>>>(wgt);
    k1_fwd<<<2048, 256, 81920>>>(x);
    k2_fwd<<<1024, 256, 81920>>>();
    k_mix<<<4096, 256>>>();
    k4_inv<<<2048, 256, 51200>>>();
    k5_inv<<<dim3(2, 2, 1024), 256, 81920>>>(bias, out);
}